// round 1
// baseline (speedup 1.0000x reference)
#include <cuda_runtime.h>

// MASLoRALinear: out = x @ W_base^T + b_base + SCALING * sum_e w[b,e] * (x @ A_e^T) @ B_e^T
// Restructured:
//   H[m, e*R+r]   = SCALING * w[b(m), e] * (x @ Acat^T)[m, e*R+r]   (Acat = As viewed (E*R, C))
//   out[m, o]     = b_base[o] + x[m,:] @ W_base[o,:] + H[m,:] @ Bcat[o,:]
//   Bcat[o, e*R+r] = Bs[e, o, r]  (prep kernel)

#define BM 128
#define BN 128
#define BK 16
#define TM 8
#define TN 8
#define NTHREADS 256

namespace {
constexpr int Bb = 16, Tt = 1500, Cc = 1024, Oo = 1024, Ee = 8, Rr = 16;
constexpr int Mm = Bb * Tt;        // 24000
constexpr int ER = Ee * Rr;        // 128
constexpr float SCALE = 32.0f / 16.0f;  // ALPHA / R = 2.0
}

// scratch (no cudaMalloc allowed)
__device__ float g_H[(size_t)Mm * ER];       // 24000 x 128
__device__ float g_Bcat[(size_t)Oo * ER];    // 1024 x 128

// ---------------------------------------------------------------------------
// prep: Bcat[o][e*R + r] = Bs[e][o][r]
// ---------------------------------------------------------------------------
__global__ void k_prep_bcat(const float* __restrict__ Bs) {
    int idx = blockIdx.x * blockDim.x + threadIdx.x;
    if (idx >= Oo * ER) return;
    int o = idx >> 7;       // / 128
    int n = idx & 127;
    int e = n >> 4;         // / 16
    int r = n & 15;
    g_Bcat[idx] = Bs[((size_t)e * Oo + o) * Rr + r];
}

// ---------------------------------------------------------------------------
// Kernel 1: H = (SCALE * w) ⊙ (x @ Acat^T)
// M=24000, N=128 (one block-col), K=1024.  BM=128, BN=128, BK=16.
// ---------------------------------------------------------------------------
__global__ __launch_bounds__(NTHREADS, 2)
void k_lora_h(const float* __restrict__ x, const float* __restrict__ As,
              const float* __restrict__ w) {
    __shared__ float sA[BK][BM];
    __shared__ float sB[BK][BN];

    const int bm = blockIdx.x * BM;
    const int tid = threadIdx.x;
    const int lr = tid >> 2;            // 0..63 loader row
    const int lc = (tid & 3) * 4;       // 0,4,8,12 loader col (float4)
    const int trow = tid >> 4;          // 0..15
    const int tcol = tid & 15;          // 0..15

    const int am0 = min(bm + lr, Mm - 1);
    const int am1 = min(bm + lr + 64, Mm - 1);
    const float* xr0 = x + (size_t)am0 * Cc + lc;
    const float* xr1 = x + (size_t)am1 * Cc + lc;
    const float* ar0 = As + (size_t)lr * Cc + lc;          // Acat rows 0..127
    const float* ar1 = As + (size_t)(lr + 64) * Cc + lc;

    float acc[TM][TN];
#pragma unroll
    for (int i = 0; i < TM; i++)
#pragma unroll
        for (int j = 0; j < TN; j++) acc[i][j] = 0.0f;

    float4 pa0 = *(const float4*)(xr0);
    float4 pa1 = *(const float4*)(xr1);
    float4 pb0 = *(const float4*)(ar0);
    float4 pb1 = *(const float4*)(ar1);

    for (int k0 = 0; k0 < Cc; k0 += BK) {
        // stage tile (transposed)
        sA[lc + 0][lr] = pa0.x; sA[lc + 1][lr] = pa0.y;
        sA[lc + 2][lr] = pa0.z; sA[lc + 3][lr] = pa0.w;
        sA[lc + 0][lr + 64] = pa1.x; sA[lc + 1][lr + 64] = pa1.y;
        sA[lc + 2][lr + 64] = pa1.z; sA[lc + 3][lr + 64] = pa1.w;
        sB[lc + 0][lr] = pb0.x; sB[lc + 1][lr] = pb0.y;
        sB[lc + 2][lr] = pb0.z; sB[lc + 3][lr] = pb0.w;
        sB[lc + 0][lr + 64] = pb1.x; sB[lc + 1][lr + 64] = pb1.y;
        sB[lc + 2][lr + 64] = pb1.z; sB[lc + 3][lr + 64] = pb1.w;
        __syncthreads();

        int kn = k0 + BK;
        if (kn < Cc) {
            pa0 = *(const float4*)(xr0 + kn);
            pa1 = *(const float4*)(xr1 + kn);
            pb0 = *(const float4*)(ar0 + kn);
            pb1 = *(const float4*)(ar1 + kn);
        }

#pragma unroll
        for (int k = 0; k < BK; k++) {
            float4 a0 = *(const float4*)&sA[k][trow * TM];
            float4 a1 = *(const float4*)&sA[k][trow * TM + 4];
            float4 b0 = *(const float4*)&sB[k][tcol * TN];
            float4 b1 = *(const float4*)&sB[k][tcol * TN + 4];
            float ra[TM] = {a0.x, a0.y, a0.z, a0.w, a1.x, a1.y, a1.z, a1.w};
            float rb[TN] = {b0.x, b0.y, b0.z, b0.w, b1.x, b1.y, b1.z, b1.w};
#pragma unroll
            for (int i = 0; i < TM; i++)
#pragma unroll
                for (int j = 0; j < TN; j++)
                    acc[i][j] += ra[i] * rb[j];
        }
        __syncthreads();
    }

    // epilogue: scale by SCALE * w[b, e]
#pragma unroll
    for (int i = 0; i < TM; i++) {
        int m = bm + trow * TM + i;
        if (m < Mm) {
            int bat = m / Tt;
#pragma unroll
            for (int j = 0; j < TN; j++) {
                int n = tcol * TN + j;
                int e = n >> 4;
                g_H[(size_t)m * ER + n] = acc[i][j] * (SCALE * __ldg(&w[bat * Ee + e]));
            }
        }
    }
}

// ---------------------------------------------------------------------------
// Kernel 2: out = x @ W_base^T + H @ Bcat^T + b_base
// M=24000, N=1024, K=1024 (+128).  BM=128, BN=128, BK=16.
// ---------------------------------------------------------------------------
__global__ __launch_bounds__(NTHREADS, 2)
void k_main(const float* __restrict__ x, const float* __restrict__ Wb,
            const float* __restrict__ bb, float* __restrict__ out) {
    __shared__ float sA[BK][BM];
    __shared__ float sB[BK][BN];

    const int bm = blockIdx.x * BM;
    const int bn = blockIdx.y * BN;
    const int tid = threadIdx.x;
    const int lr = tid >> 2;
    const int lc = (tid & 3) * 4;
    const int trow = tid >> 4;
    const int tcol = tid & 15;

    const int am0 = min(bm + lr, Mm - 1);
    const int am1 = min(bm + lr + 64, Mm - 1);

    float acc[TM][TN];
#pragma unroll
    for (int i = 0; i < TM; i++)
#pragma unroll
        for (int j = 0; j < TN; j++) acc[i][j] = 0.0f;

    // ---- Phase 1: K = 1024 over x / W_base ----
    {
        const float* xr0 = x + (size_t)am0 * Cc + lc;
        const float* xr1 = x + (size_t)am1 * Cc + lc;
        const float* wr0 = Wb + (size_t)(bn + lr) * Cc + lc;
        const float* wr1 = Wb + (size_t)(bn + lr + 64) * Cc + lc;

        float4 pa0 = *(const float4*)(xr0);
        float4 pa1 = *(const float4*)(xr1);
        float4 pb0 = *(const float4*)(wr0);
        float4 pb1 = *(const float4*)(wr1);

        for (int k0 = 0; k0 < Cc; k0 += BK) {
            sA[lc + 0][lr] = pa0.x; sA[lc + 1][lr] = pa0.y;
            sA[lc + 2][lr] = pa0.z; sA[lc + 3][lr] = pa0.w;
            sA[lc + 0][lr + 64] = pa1.x; sA[lc + 1][lr + 64] = pa1.y;
            sA[lc + 2][lr + 64] = pa1.z; sA[lc + 3][lr + 64] = pa1.w;
            sB[lc + 0][lr] = pb0.x; sB[lc + 1][lr] = pb0.y;
            sB[lc + 2][lr] = pb0.z; sB[lc + 3][lr] = pb0.w;
            sB[lc + 0][lr + 64] = pb1.x; sB[lc + 1][lr + 64] = pb1.y;
            sB[lc + 2][lr + 64] = pb1.z; sB[lc + 3][lr + 64] = pb1.w;
            __syncthreads();

            int kn = k0 + BK;
            if (kn < Cc) {
                pa0 = *(const float4*)(xr0 + kn);
                pa1 = *(const float4*)(xr1 + kn);
                pb0 = *(const float4*)(wr0 + kn);
                pb1 = *(const float4*)(wr1 + kn);
            }

#pragma unroll
            for (int k = 0; k < BK; k++) {
                float4 a0 = *(const float4*)&sA[k][trow * TM];
                float4 a1 = *(const float4*)&sA[k][trow * TM + 4];
                float4 b0 = *(const float4*)&sB[k][tcol * TN];
                float4 b1 = *(const float4*)&sB[k][tcol * TN + 4];
                float ra[TM] = {a0.x, a0.y, a0.z, a0.w, a1.x, a1.y, a1.z, a1.w};
                float rb[TN] = {b0.x, b0.y, b0.z, b0.w, b1.x, b1.y, b1.z, b1.w};
#pragma unroll
                for (int i = 0; i < TM; i++)
#pragma unroll
                    for (int j = 0; j < TN; j++)
                        acc[i][j] += ra[i] * rb[j];
            }
            __syncthreads();
        }
    }

    // ---- Phase 2: K = 128 over H / Bcat ----
    {
        const float* hr0 = g_H + (size_t)am0 * ER + lc;
        const float* hr1 = g_H + (size_t)am1 * ER + lc;
        const float* br0 = g_Bcat + (size_t)(bn + lr) * ER + lc;
        const float* br1 = g_Bcat + (size_t)(bn + lr + 64) * ER + lc;

        float4 pa0 = *(const float4*)(hr0);
        float4 pa1 = *(const float4*)(hr1);
        float4 pb0 = *(const float4*)(br0);
        float4 pb1 = *(const float4*)(br1);

        for (int k0 = 0; k0 < ER; k0 += BK) {
            sA[lc + 0][lr] = pa0.x; sA[lc + 1][lr] = pa0.y;
            sA[lc + 2][lr] = pa0.z; sA[lc + 3][lr] = pa0.w;
            sA[lc + 0][lr + 64] = pa1.x; sA[lc + 1][lr + 64] = pa1.y;
            sA[lc + 2][lr + 64] = pa1.z; sA[lc + 3][lr + 64] = pa1.w;
            sB[lc + 0][lr] = pb0.x; sB[lc + 1][lr] = pb0.y;
            sB[lc + 2][lr] = pb0.z; sB[lc + 3][lr] = pb0.w;
            sB[lc + 0][lr + 64] = pb1.x; sB[lc + 1][lr + 64] = pb1.y;
            sB[lc + 2][lr + 64] = pb1.z; sB[lc + 3][lr + 64] = pb1.w;
            __syncthreads();

            int kn = k0 + BK;
            if (kn < ER) {
                pa0 = *(const float4*)(hr0 + kn);
                pa1 = *(const float4*)(hr1 + kn);
                pb0 = *(const float4*)(br0 + kn);
                pb1 = *(const float4*)(br1 + kn);
            }

#pragma unroll
            for (int k = 0; k < BK; k++) {
                float4 a0 = *(const float4*)&sA[k][trow * TM];
                float4 a1 = *(const float4*)&sA[k][trow * TM + 4];
                float4 b0 = *(const float4*)&sB[k][tcol * TN];
                float4 b1 = *(const float4*)&sB[k][tcol * TN + 4];
                float ra[TM] = {a0.x, a0.y, a0.z, a0.w, a1.x, a1.y, a1.z, a1.w};
                float rb[TN] = {b0.x, b0.y, b0.z, b0.w, b1.x, b1.y, b1.z, b1.w};
#pragma unroll
                for (int i = 0; i < TM; i++)
#pragma unroll
                    for (int j = 0; j < TN; j++)
                        acc[i][j] += ra[i] * rb[j];
            }
            __syncthreads();
        }
    }

    // ---- Epilogue: add bias, store ----
    float bias[TN];
#pragma unroll
    for (int j = 0; j < TN; j++) bias[j] = __ldg(&bb[bn + tcol * TN + j]);

#pragma unroll
    for (int i = 0; i < TM; i++) {
        int m = bm + trow * TM + i;
        if (m < Mm) {
            float* orow = out + (size_t)m * Oo + bn + tcol * TN;
            float4 o0, o1;
            o0.x = acc[i][0] + bias[0]; o0.y = acc[i][1] + bias[1];
            o0.z = acc[i][2] + bias[2]; o0.w = acc[i][3] + bias[3];
            o1.x = acc[i][4] + bias[4]; o1.y = acc[i][5] + bias[5];
            o1.z = acc[i][6] + bias[6]; o1.w = acc[i][7] + bias[7];
            *(float4*)(orow) = o0;
            *(float4*)(orow + 4) = o1;
        }
    }
}

// ---------------------------------------------------------------------------
extern "C" void kernel_launch(void* const* d_in, const int* in_sizes, int n_in,
                              void* d_out, int out_size) {
    const float* x  = (const float*)d_in[0];   // (16,1500,1024)
    const float* w  = (const float*)d_in[1];   // (16,8)
    const float* Wb = (const float*)d_in[2];   // (1024,1024)
    const float* bb = (const float*)d_in[3];   // (1024,)
    const float* As = (const float*)d_in[4];   // (8,16,1024)
    const float* Bs = (const float*)d_in[5];   // (8,1024,16)
    float* out = (float*)d_out;                // (16,1500,1024)

    k_prep_bcat<<<(Oo * ER + 255) / 256, 256>>>(Bs);

    int grid_m = (Mm + BM - 1) / BM;   // 188
    k_lora_h<<<grid_m, NTHREADS>>>(x, As, w);

    dim3 g2(grid_m, Oo / BN);          // 188 x 8
    k_main<<<g2, NTHREADS>>>(x, Wb, bb, out);
}

// round 3
// speedup vs baseline: 2.1076x; 2.1076x over previous
#include <cuda_runtime.h>
#include <cuda_bf16.h>
#include <cstdint>

// MASLoRALinear via HMMA (mma.sync bf16) with fp32 accuracy via hi/lo split:
//   each fp32 operand = hi(bf16) + lo(bf16); product = hh + hl + lh (ll dropped, ~4e-6)
//   H[m, e*R+r] = SCALE * w[b(m), e] * (x @ Acat^T)[m, n]
//   out[m, o]   = b_base[o] + x[m,:]@W_base[o,:] + H[m,:]@Bcat[o,:]

namespace {
constexpr int Tt = 1500, Cc = 1024, Oo = 1024, Ee = 8, Rr = 16;
constexpr int Mm = 16 * Tt;          // 24000
constexpr int ER = Ee * Rr;          // 128
constexpr float SCALE = 32.0f / 16.0f;
constexpr int DYN_SMEM = 65536;      // 2 stages x (Ahi,Alo,Bhi,Blo) x 8KB
}

__device__ float g_H[(size_t)Mm * ER];
__device__ float g_Bcat[(size_t)Oo * ER];

// ---------------------------------------------------------------------------
__device__ __forceinline__ uint32_t smem_u32(const void* p) {
    uint32_t a;
    asm("{ .reg .u64 t; cvta.to.shared.u64 t, %1; cvt.u32.u64 %0, t; }" : "=r"(a) : "l"(p));
    return a;
}

#define LDSM_X4(r0, r1, r2, r3, a) \
    asm volatile("ldmatrix.sync.aligned.m8n8.x4.shared.b16 {%0,%1,%2,%3}, [%4];" \
                 : "=r"(r0), "=r"(r1), "=r"(r2), "=r"(r3) : "r"(a))

#define MMA_BF16(d, a, b) \
    asm volatile("mma.sync.aligned.m16n8k16.row.col.f32.bf16.bf16.f32 " \
                 "{%0,%1,%2,%3},{%4,%5,%6,%7},{%8,%9},{%0,%1,%2,%3};" \
                 : "+f"((d)[0]), "+f"((d)[1]), "+f"((d)[2]), "+f"((d)[3]) \
                 : "r"((a)[0]), "r"((a)[1]), "r"((a)[2]), "r"((a)[3]), \
                   "r"((b)[0]), "r"((b)[1]))

// fp32 x4 -> bf16 hi/lo, 8B store each
__device__ __forceinline__ void sts_pair(uint32_t hiA, uint32_t loA, float4 v) {
    __nv_bfloat162 H0 = __float22bfloat162_rn(make_float2(v.x, v.y));
    __nv_bfloat162 H1 = __float22bfloat162_rn(make_float2(v.z, v.w));
    float2 f0 = __bfloat1622float2(H0);
    float2 f1 = __bfloat1622float2(H1);
    __nv_bfloat162 L0 = __float22bfloat162_rn(make_float2(v.x - f0.x, v.y - f0.y));
    __nv_bfloat162 L1 = __float22bfloat162_rn(make_float2(v.z - f1.x, v.w - f1.y));
    uint32_t h0 = *(uint32_t*)&H0, h1 = *(uint32_t*)&H1;
    uint32_t l0 = *(uint32_t*)&L0, l1 = *(uint32_t*)&L1;
    asm volatile("st.shared.v2.b32 [%0], {%1,%2};" :: "r"(hiA), "r"(h0), "r"(h1));
    asm volatile("st.shared.v2.b32 [%0], {%1,%2};" :: "r"(loA), "r"(l0), "r"(l1));
}

// stage one 128x32 fp32 tile (this thread's slice): row = tid>>1, half = tid&1
__device__ __forceinline__ void sts_tile(const float4* pre, int row, int half,
                                         uint32_t hiB, uint32_t loB) {
#pragma unroll
    for (int i = 0; i < 4; i++) {
        int c = half * 2 + (i >> 1);
        uint32_t off = (uint32_t)(row * 64 + ((c ^ ((row >> 1) & 3)) << 4) + (i & 1) * 8);
        sts_pair(hiB + off, loB + off, pre[i]);
    }
}

__device__ __forceinline__ void ldg4(float4* pre, const float* rowptr, int half) {
#pragma unroll
    for (int i = 0; i < 4; i++) pre[i] = *(const float4*)(rowptr + half * 16 + i * 4);
}

// one BK=32 chunk: 2 k-steps x (4 m-tiles x 4 n-tiles) x 3 split products
__device__ __forceinline__ void compute_chunk(float (&acc)[4][4][4],
                                              uint32_t base,
                                              const uint32_t* offA,   // [mi*2+ks]
                                              const uint32_t* offB) { // [j*2+ks]
    const uint32_t aHiB = base, aLoB = base + 8192u;
    const uint32_t bHiB = base + 16384u, bLoB = base + 24576u;
#pragma unroll
    for (int ks = 0; ks < 2; ks++) {
        uint32_t aH[4][4], aL[4][4], bH[4][2], bL[4][2];
#pragma unroll
        for (int mi = 0; mi < 4; mi++) {
            uint32_t o = offA[mi * 2 + ks];
            LDSM_X4(aH[mi][0], aH[mi][1], aH[mi][2], aH[mi][3], aHiB + o);
            LDSM_X4(aL[mi][0], aL[mi][1], aL[mi][2], aL[mi][3], aLoB + o);
        }
#pragma unroll
        for (int j = 0; j < 2; j++) {
            uint32_t o = offB[j * 2 + ks];
            uint32_t t0, t1, t2, t3;
            LDSM_X4(t0, t1, t2, t3, bHiB + o);
            bH[2 * j][0] = t0; bH[2 * j][1] = t1;
            bH[2 * j + 1][0] = t2; bH[2 * j + 1][1] = t3;
            LDSM_X4(t0, t1, t2, t3, bLoB + o);
            bL[2 * j][0] = t0; bL[2 * j][1] = t1;
            bL[2 * j + 1][0] = t2; bL[2 * j + 1][1] = t3;
        }
#pragma unroll
        for (int mi = 0; mi < 4; mi++)
#pragma unroll
            for (int ni = 0; ni < 4; ni++) {
                MMA_BF16(acc[mi][ni], aH[mi], bH[ni]);
                MMA_BF16(acc[mi][ni], aH[mi], bL[ni]);
                MMA_BF16(acc[mi][ni], aL[mi], bH[ni]);
            }
    }
}

// precompute per-lane swizzled ldmatrix offsets
__device__ __forceinline__ void make_offsets(int lane, int wm, int wn,
                                             uint32_t* offA, uint32_t* offB) {
    int g = lane >> 3, wr = lane & 7;
#pragma unroll
    for (int mi = 0; mi < 4; mi++)
#pragma unroll
        for (int ks = 0; ks < 2; ks++) {
            int r = wm * 64 + mi * 16 + (g & 1) * 8 + wr;
            int c = ks * 2 + (g >> 1);
            offA[mi * 2 + ks] = (uint32_t)(r * 64 + ((c ^ ((r >> 1) & 3)) << 4));
        }
#pragma unroll
    for (int j = 0; j < 2; j++)
#pragma unroll
        for (int ks = 0; ks < 2; ks++) {
            int n = wn * 32 + j * 16 + (g >> 1) * 8 + wr;
            int c = ks * 2 + (g & 1);
            offB[j * 2 + ks] = (uint32_t)(n * 64 + ((c ^ ((n >> 1) & 3)) << 4));
        }
}

// ---------------------------------------------------------------------------
__global__ void k_prep_bcat(const float* __restrict__ Bs) {
    int idx = blockIdx.x * blockDim.x + threadIdx.x;
    if (idx >= Oo * ER) return;
    int o = idx >> 7;
    int n = idx & 127;
    int e = n >> 4;
    int r = n & 15;
    g_Bcat[idx] = Bs[((size_t)e * Oo + o) * Rr + r];
}

// ---------------------------------------------------------------------------
// Kernel 1: H = gate-scaled (x @ Acat^T), K=1024 (32 chunks), N=128
// ---------------------------------------------------------------------------
__global__ __launch_bounds__(256, 1)
void k_lora_h(const float* __restrict__ x, const float* __restrict__ As,
              const float* __restrict__ w) {
    extern __shared__ char dsm[];
    const uint32_t sb = smem_u32(dsm);
    const int tid = threadIdx.x;
    const int lane = tid & 31, wid = tid >> 5;
    const int wm = wid >> 2, wn = wid & 3;
    const int bm = blockIdx.x * 128;

    const int row = tid >> 1, half = tid & 1;
    const size_t mA = (size_t)min(bm + row, Mm - 1);
    const float* xrow = x + mA * Cc;
    const float* arow = As + (size_t)row * Cc;   // Acat rows 0..127

    uint32_t offA[8], offB[4];
    make_offsets(lane, wm, wn, offA, offB);

    float acc[4][4][4];
#pragma unroll
    for (int a = 0; a < 4; a++)
#pragma unroll
        for (int b = 0; b < 4; b++)
#pragma unroll
            for (int c = 0; c < 4; c++) acc[a][b][c] = 0.0f;

    float4 preA[4], preB[4];
    ldg4(preA, xrow, half);
    ldg4(preB, arow, half);
    sts_tile(preA, row, half, sb, sb + 8192u);
    sts_tile(preB, row, half, sb + 16384u, sb + 24576u);
    __syncthreads();

    const int NCH = 32;
#pragma unroll 1
    for (int ch = 0; ch < NCH; ch++) {
        const int s = ch & 1;
        if (ch + 1 < NCH) {
            ldg4(preA, xrow + (ch + 1) * 32, half);
            ldg4(preB, arow + (ch + 1) * 32, half);
        }
        compute_chunk(acc, sb + (uint32_t)s * 32768u, offA, offB);
        __syncthreads();
        if (ch + 1 < NCH) {
            uint32_t nb = sb + (uint32_t)(s ^ 1) * 32768u;
            sts_tile(preA, row, half, nb, nb + 8192u);
            sts_tile(preB, row, half, nb + 16384u, nb + 24576u);
            __syncthreads();
        }
    }

    // epilogue: scale by SCALE * w[b(m), e] and store to g_H
#pragma unroll
    for (int mi = 0; mi < 4; mi++) {
#pragma unroll
        for (int ni = 0; ni < 4; ni++) {
            int n = wn * 32 + ni * 8 + 2 * (lane & 3);
            int e = n >> 4;
            int m0 = bm + wm * 64 + mi * 16 + (lane >> 2);
            if (m0 < Mm) {
                float sw = SCALE * __ldg(&w[(m0 / Tt) * Ee + e]);
                float2 o = make_float2(acc[mi][ni][0] * sw, acc[mi][ni][1] * sw);
                *(float2*)(&g_H[(size_t)m0 * ER + n]) = o;
            }
            int m1 = m0 + 8;
            if (m1 < Mm) {
                float sw = SCALE * __ldg(&w[(m1 / Tt) * Ee + e]);
                float2 o = make_float2(acc[mi][ni][2] * sw, acc[mi][ni][3] * sw);
                *(float2*)(&g_H[(size_t)m1 * ER + n]) = o;
            }
        }
    }
}

// ---------------------------------------------------------------------------
// Kernel 2: out = x @ W_base^T + H @ Bcat^T + b_base
// 36 chunks: 32 of K=1024 (x/Wb) + 4 of K=128 (H/Bcat)
// ---------------------------------------------------------------------------
__global__ __launch_bounds__(256, 1)
void k_main(const float* __restrict__ x, const float* __restrict__ Wb,
            const float* __restrict__ bb, float* __restrict__ out) {
    extern __shared__ char dsm[];
    const uint32_t sb = smem_u32(dsm);
    const int tid = threadIdx.x;
    const int lane = tid & 31, wid = tid >> 5;
    const int wm = wid >> 2, wn = wid & 3;
    const int bn = blockIdx.x * 128;
    const int bm = blockIdx.y * 128;

    const int row = tid >> 1, half = tid & 1;
    const size_t mA = (size_t)min(bm + row, Mm - 1);
    const float* xrow = x + mA * Cc;
    const float* wrow = Wb + (size_t)(bn + row) * Cc;
    const float* hrow = g_H + mA * ER;
    const float* brow = g_Bcat + (size_t)(bn + row) * ER;

    uint32_t offA[8], offB[4];
    make_offsets(lane, wm, wn, offA, offB);

    float acc[4][4][4];
#pragma unroll
    for (int a = 0; a < 4; a++)
#pragma unroll
        for (int b = 0; b < 4; b++)
#pragma unroll
            for (int c = 0; c < 4; c++) acc[a][b][c] = 0.0f;

    float4 preA[4], preB[4];
    ldg4(preA, xrow, half);
    ldg4(preB, wrow, half);
    sts_tile(preA, row, half, sb, sb + 8192u);
    sts_tile(preB, row, half, sb + 16384u, sb + 24576u);
    __syncthreads();

    const int NCH = 36;
#pragma unroll 1
    for (int ch = 0; ch < NCH; ch++) {
        const int s = ch & 1;
        if (ch + 1 < NCH) {
            const float *pa, *pb;
            if (ch + 1 < 32) {
                pa = xrow + (ch + 1) * 32;
                pb = wrow + (ch + 1) * 32;
            } else {
                pa = hrow + (ch + 1 - 32) * 32;
                pb = brow + (ch + 1 - 32) * 32;
            }
            ldg4(preA, pa, half);
            ldg4(preB, pb, half);
        }
        compute_chunk(acc, sb + (uint32_t)s * 32768u, offA, offB);
        __syncthreads();
        if (ch + 1 < NCH) {
            uint32_t nb = sb + (uint32_t)(s ^ 1) * 32768u;
            sts_tile(preA, row, half, nb, nb + 8192u);
            sts_tile(preB, row, half, nb + 16384u, nb + 24576u);
            __syncthreads();
        }
    }

    // epilogue: add bias, store
#pragma unroll
    for (int mi = 0; mi < 4; mi++) {
#pragma unroll
        for (int ni = 0; ni < 4; ni++) {
            int col = bn + wn * 32 + ni * 8 + 2 * (lane & 3);
            float2 bias = *(const float2*)(bb + col);
            int m0 = bm + wm * 64 + mi * 16 + (lane >> 2);
            if (m0 < Mm) {
                float2 o = make_float2(acc[mi][ni][0] + bias.x, acc[mi][ni][1] + bias.y);
                *(float2*)(out + (size_t)m0 * Oo + col) = o;
            }
            int m1 = m0 + 8;
            if (m1 < Mm) {
                float2 o = make_float2(acc[mi][ni][2] + bias.x, acc[mi][ni][3] + bias.y);
                *(float2*)(out + (size_t)m1 * Oo + col) = o;
            }
        }
    }
}

// ---------------------------------------------------------------------------
extern "C" void kernel_launch(void* const* d_in, const int* in_sizes, int n_in,
                              void* d_out, int out_size) {
    const float* x  = (const float*)d_in[0];   // (16,1500,1024)
    const float* w  = (const float*)d_in[1];   // (16,8)
    const float* Wb = (const float*)d_in[2];   // (1024,1024)
    const float* bb = (const float*)d_in[3];   // (1024,)
    const float* As = (const float*)d_in[4];   // (8,16,1024)
    const float* Bs = (const float*)d_in[5];   // (8,1024,16)
    float* out = (float*)d_out;

    cudaFuncSetAttribute(k_lora_h, cudaFuncAttributeMaxDynamicSharedMemorySize, DYN_SMEM);
    cudaFuncSetAttribute(k_main, cudaFuncAttributeMaxDynamicSharedMemorySize, DYN_SMEM);

    k_prep_bcat<<<(Oo * ER + 255) / 256, 256>>>(Bs);

    const int grid_m = (Mm + 127) / 128;  // 188
    k_lora_h<<<grid_m, 256, DYN_SMEM>>>(x, As, w);

    dim3 g2(Oo / 128, grid_m);            // (8, 188)
    k_main<<<g2, 256, DYN_SMEM>>>(x, Wb, bb, out);
}

// round 4
// speedup vs baseline: 2.7244x; 1.2927x over previous
#include <cuda_runtime.h>
#include <cuda_fp16.h>
#include <cstdint>

// MASLoRALinear via single-pass fp16 HMMA (mma.sync m16n8k16 f16->f32):
//   H[m, e*R+r] = SCALE * w[b(m), e] * (x @ Acat^T)[m, n]
//   out[m, o]   = b_base[o] + x[m,:]@W_base[o,:] + H[m,:]@Bcat[o,:]
// fp16 rounding (2^-12 RMS per operand) -> aggregate rel_err ~2e-4 < 1e-3.

namespace {
constexpr int Tt = 1500, Cc = 1024, Oo = 1024, Ee = 8, Rr = 16;
constexpr int Mm = 16 * Tt;          // 24000
constexpr int ER = Ee * Rr;          // 128
constexpr float SCALE = 32.0f / 16.0f;
constexpr int STAGE = 16384;         // A(8KB) + B(8KB) fp16
constexpr int DYN_SMEM = 2 * STAGE;  // double buffered
}

__device__ float g_H[(size_t)Mm * ER];
__device__ float g_Bcat[(size_t)Oo * ER];

// ---------------------------------------------------------------------------
__device__ __forceinline__ uint32_t smem_u32(const void* p) {
    uint32_t a;
    asm("{ .reg .u64 t; cvta.to.shared.u64 t, %1; cvt.u32.u64 %0, t; }" : "=r"(a) : "l"(p));
    return a;
}

#define LDSM_X4(r0, r1, r2, r3, a) \
    asm volatile("ldmatrix.sync.aligned.m8n8.x4.shared.b16 {%0,%1,%2,%3}, [%4];" \
                 : "=r"(r0), "=r"(r1), "=r"(r2), "=r"(r3) : "r"(a))

#define MMA_F16(d, a, b) \
    asm volatile("mma.sync.aligned.m16n8k16.row.col.f32.f16.f16.f32 " \
                 "{%0,%1,%2,%3},{%4,%5,%6,%7},{%8,%9},{%0,%1,%2,%3};" \
                 : "+f"((d)[0]), "+f"((d)[1]), "+f"((d)[2]), "+f"((d)[3]) \
                 : "r"((a)[0]), "r"((a)[1]), "r"((a)[2]), "r"((a)[3]), \
                   "r"((b)[0]), "r"((b)[1]))

// fp32 x4 -> fp16 x4, one 8B smem store
__device__ __forceinline__ void sts_h(uint32_t addr, float4 v) {
    __half2 h0 = __float22half2_rn(make_float2(v.x, v.y));
    __half2 h1 = __float22half2_rn(make_float2(v.z, v.w));
    uint32_t u0 = *(uint32_t*)&h0, u1 = *(uint32_t*)&h1;
    asm volatile("st.shared.v2.b32 [%0], {%1,%2};" :: "r"(addr), "r"(u0), "r"(u1));
}

// stage one 128x32 fp32 tile: row = tid>>1, half = tid&1 (16 cols each)
__device__ __forceinline__ void sts_tile(const float4* pre, int row, int half, uint32_t base) {
#pragma unroll
    for (int i = 0; i < 4; i++) {
        int c = half * 2 + (i >> 1);  // 16B column index 0..3
        uint32_t off = (uint32_t)(row * 64 + ((c ^ ((row >> 1) & 3)) << 4) + (i & 1) * 8);
        sts_h(base + off, pre[i]);
    }
}

__device__ __forceinline__ void ldg4(float4* pre, const float* rowptr, int half) {
#pragma unroll
    for (int i = 0; i < 4; i++) pre[i] = *(const float4*)(rowptr + half * 16 + i * 4);
}

// one BK=32 chunk: 2 k-steps x (4 m-tiles x 4 n-tiles)
__device__ __forceinline__ void compute_chunk(float (&acc)[4][4][4],
                                              uint32_t base,
                                              const uint32_t* offA,   // [mi*2+ks]
                                              const uint32_t* offB) { // [j*2+ks]
    const uint32_t aB = base, bB = base + 8192u;
#pragma unroll
    for (int ks = 0; ks < 2; ks++) {
        uint32_t aF[4][4], bF[4][2];
#pragma unroll
        for (int mi = 0; mi < 4; mi++)
            LDSM_X4(aF[mi][0], aF[mi][1], aF[mi][2], aF[mi][3], aB + offA[mi * 2 + ks]);
#pragma unroll
        for (int j = 0; j < 2; j++) {
            uint32_t t0, t1, t2, t3;
            LDSM_X4(t0, t1, t2, t3, bB + offB[j * 2 + ks]);
            bF[2 * j][0] = t0; bF[2 * j][1] = t1;
            bF[2 * j + 1][0] = t2; bF[2 * j + 1][1] = t3;
        }
#pragma unroll
        for (int mi = 0; mi < 4; mi++)
#pragma unroll
            for (int ni = 0; ni < 4; ni++)
                MMA_F16(acc[mi][ni], aF[mi], bF[ni]);
    }
}

// per-lane swizzled ldmatrix offsets (64B rows, 4x16B columns, xor swizzle)
__device__ __forceinline__ void make_offsets(int lane, int wm, int wn,
                                             uint32_t* offA, uint32_t* offB) {
    int g = lane >> 3, wr = lane & 7;
#pragma unroll
    for (int mi = 0; mi < 4; mi++)
#pragma unroll
        for (int ks = 0; ks < 2; ks++) {
            int r = wm * 64 + mi * 16 + (g & 1) * 8 + wr;
            int c = ks * 2 + (g >> 1);
            offA[mi * 2 + ks] = (uint32_t)(r * 64 + ((c ^ ((r >> 1) & 3)) << 4));
        }
#pragma unroll
    for (int j = 0; j < 2; j++)
#pragma unroll
        for (int ks = 0; ks < 2; ks++) {
            int n = wn * 32 + j * 16 + (g >> 1) * 8 + wr;
            int c = ks * 2 + (g & 1);
            offB[j * 2 + ks] = (uint32_t)(n * 64 + ((c ^ ((n >> 1) & 3)) << 4));
        }
}

// ---------------------------------------------------------------------------
__global__ void k_prep_bcat(const float* __restrict__ Bs) {
    int idx = blockIdx.x * blockDim.x + threadIdx.x;
    if (idx >= Oo * ER) return;
    int o = idx >> 7;
    int n = idx & 127;
    int e = n >> 4;
    int r = n & 15;
    g_Bcat[idx] = Bs[((size_t)e * Oo + o) * Rr + r];
}

// ---------------------------------------------------------------------------
// Kernel 1: H = gate-scaled (x @ Acat^T), K=1024 (32 chunks), N=128
// ---------------------------------------------------------------------------
__global__ __launch_bounds__(256, 1)
void k_lora_h(const float* __restrict__ x, const float* __restrict__ As,
              const float* __restrict__ w) {
    extern __shared__ char dsm[];
    const uint32_t sb = smem_u32(dsm);
    const int tid = threadIdx.x;
    const int lane = tid & 31, wid = tid >> 5;
    const int wm = wid >> 2, wn = wid & 3;
    const int bm = blockIdx.x * 128;

    const int row = tid >> 1, half = tid & 1;
    const size_t mA = (size_t)min(bm + row, Mm - 1);
    const float* xrow = x + mA * Cc;
    const float* arow = As + (size_t)row * Cc;   // Acat rows 0..127

    uint32_t offA[8], offB[4];
    make_offsets(lane, wm, wn, offA, offB);

    float acc[4][4][4];
#pragma unroll
    for (int a = 0; a < 4; a++)
#pragma unroll
        for (int b = 0; b < 4; b++)
#pragma unroll
            for (int c = 0; c < 4; c++) acc[a][b][c] = 0.0f;

    float4 preA[4], preB[4];
    ldg4(preA, xrow, half);
    ldg4(preB, arow, half);
    sts_tile(preA, row, half, sb);
    sts_tile(preB, row, half, sb + 8192u);
    __syncthreads();

    const int NCH = 32;
#pragma unroll 1
    for (int ch = 0; ch < NCH; ch++) {
        const int s = ch & 1;
        if (ch + 1 < NCH) {
            ldg4(preA, xrow + (ch + 1) * 32, half);
            ldg4(preB, arow + (ch + 1) * 32, half);
        }
        compute_chunk(acc, sb + (uint32_t)s * STAGE, offA, offB);
        __syncthreads();
        if (ch + 1 < NCH) {
            uint32_t nb = sb + (uint32_t)(s ^ 1) * STAGE;
            sts_tile(preA, row, half, nb);
            sts_tile(preB, row, half, nb + 8192u);
            __syncthreads();
        }
    }

    // epilogue: scale by SCALE * w[b(m), e] and store to g_H
#pragma unroll
    for (int mi = 0; mi < 4; mi++) {
#pragma unroll
        for (int ni = 0; ni < 4; ni++) {
            int n = wn * 32 + ni * 8 + 2 * (lane & 3);
            int e = n >> 4;
            int m0 = bm + wm * 64 + mi * 16 + (lane >> 2);
            if (m0 < Mm) {
                float sw = SCALE * __ldg(&w[(m0 / Tt) * Ee + e]);
                float2 o = make_float2(acc[mi][ni][0] * sw, acc[mi][ni][1] * sw);
                *(float2*)(&g_H[(size_t)m0 * ER + n]) = o;
            }
            int m1 = m0 + 8;
            if (m1 < Mm) {
                float sw = SCALE * __ldg(&w[(m1 / Tt) * Ee + e]);
                float2 o = make_float2(acc[mi][ni][2] * sw, acc[mi][ni][3] * sw);
                *(float2*)(&g_H[(size_t)m1 * ER + n]) = o;
            }
        }
    }
}

// ---------------------------------------------------------------------------
// Kernel 2: out = x @ W_base^T + H @ Bcat^T + b_base
// 36 chunks: 32 of K=1024 (x/Wb) + 4 of K=128 (H/Bcat)
// ---------------------------------------------------------------------------
__global__ __launch_bounds__(256, 1)
void k_main(const float* __restrict__ x, const float* __restrict__ Wb,
            const float* __restrict__ bb, float* __restrict__ out) {
    extern __shared__ char dsm[];
    const uint32_t sb = smem_u32(dsm);
    const int tid = threadIdx.x;
    const int lane = tid & 31, wid = tid >> 5;
    const int wm = wid >> 2, wn = wid & 3;
    const int bn = blockIdx.x * 128;
    const int bm = blockIdx.y * 128;

    const int row = tid >> 1, half = tid & 1;
    const size_t mA = (size_t)min(bm + row, Mm - 1);
    const float* xrow = x + mA * Cc;
    const float* wrow = Wb + (size_t)(bn + row) * Cc;
    const float* hrow = g_H + mA * ER;
    const float* brow = g_Bcat + (size_t)(bn + row) * ER;

    uint32_t offA[8], offB[4];
    make_offsets(lane, wm, wn, offA, offB);

    float acc[4][4][4];
#pragma unroll
    for (int a = 0; a < 4; a++)
#pragma unroll
        for (int b = 0; b < 4; b++)
#pragma unroll
            for (int c = 0; c < 4; c++) acc[a][b][c] = 0.0f;

    float4 preA[4], preB[4];
    ldg4(preA, xrow, half);
    ldg4(preB, wrow, half);
    sts_tile(preA, row, half, sb);
    sts_tile(preB, row, half, sb + 8192u);
    __syncthreads();

    const int NCH = 36;
#pragma unroll 1
    for (int ch = 0; ch < NCH; ch++) {
        const int s = ch & 1;
        if (ch + 1 < NCH) {
            const float *pa, *pb;
            if (ch + 1 < 32) {
                pa = xrow + (ch + 1) * 32;
                pb = wrow + (ch + 1) * 32;
            } else {
                pa = hrow + (ch + 1 - 32) * 32;
                pb = brow + (ch + 1 - 32) * 32;
            }
            ldg4(preA, pa, half);
            ldg4(preB, pb, half);
        }
        compute_chunk(acc, sb + (uint32_t)s * STAGE, offA, offB);
        __syncthreads();
        if (ch + 1 < NCH) {
            uint32_t nb = sb + (uint32_t)(s ^ 1) * STAGE;
            sts_tile(preA, row, half, nb);
            sts_tile(preB, row, half, nb + 8192u);
            __syncthreads();
        }
    }

    // epilogue: add bias, store
#pragma unroll
    for (int mi = 0; mi < 4; mi++) {
#pragma unroll
        for (int ni = 0; ni < 4; ni++) {
            int col = bn + wn * 32 + ni * 8 + 2 * (lane & 3);
            float2 bias = *(const float2*)(bb + col);
            int m0 = bm + wm * 64 + mi * 16 + (lane >> 2);
            if (m0 < Mm) {
                float2 o = make_float2(acc[mi][ni][0] + bias.x, acc[mi][ni][1] + bias.y);
                *(float2*)(out + (size_t)m0 * Oo + col) = o;
            }
            int m1 = m0 + 8;
            if (m1 < Mm) {
                float2 o = make_float2(acc[mi][ni][2] + bias.x, acc[mi][ni][3] + bias.y);
                *(float2*)(out + (size_t)m1 * Oo + col) = o;
            }
        }
    }
}

// ---------------------------------------------------------------------------
extern "C" void kernel_launch(void* const* d_in, const int* in_sizes, int n_in,
                              void* d_out, int out_size) {
    const float* x  = (const float*)d_in[0];   // (16,1500,1024)
    const float* w  = (const float*)d_in[1];   // (16,8)
    const float* Wb = (const float*)d_in[2];   // (1024,1024)
    const float* bb = (const float*)d_in[3];   // (1024,)
    const float* As = (const float*)d_in[4];   // (8,16,1024)
    const float* Bs = (const float*)d_in[5];   // (8,1024,16)
    float* out = (float*)d_out;

    cudaFuncSetAttribute(k_lora_h, cudaFuncAttributeMaxDynamicSharedMemorySize, DYN_SMEM);
    cudaFuncSetAttribute(k_main, cudaFuncAttributeMaxDynamicSharedMemorySize, DYN_SMEM);

    k_prep_bcat<<<(Oo * ER + 255) / 256, 256>>>(Bs);

    const int grid_m = (Mm + 127) / 128;  // 188
    k_lora_h<<<grid_m, 256, DYN_SMEM>>>(x, As, w);

    dim3 g2(Oo / 128, grid_m);            // (8, 188)
    k_main<<<g2, 256, DYN_SMEM>>>(x, Wb, bb, out);
}

// round 8
// speedup vs baseline: 6.6348x; 2.4353x over previous
#include <cuda_runtime.h>
#include <cuda_fp16.h>
#include <cstdint>

// MASLoRALinear, fp16 HMMA with cp.async 3-stage pipeline.
//   pre: xh=half(x), wbh=half(W_base), ah=half(Acat), bch=half(Bcat)  [in device code!]
//   K1:  Hh[m,n] = half( SCALE * w[b(m), n>>4] * (xh @ ah^T)[m,n] )
//   K2:  out[m,o] = bb[o] + (xh @ wbh^T)[m,o] + (Hh @ bch^T)[m,o]

namespace {
constexpr int Tt = 1500, Cc = 1024, Oo = 1024, Ee = 8, Rr = 16;
constexpr int Mm = 16 * Tt;          // 24000
constexpr int ER = Ee * Rr;          // 128
constexpr float SCALE = 32.0f / 16.0f;
constexpr int STAGE = 16384;         // A 8KB + B 8KB (fp16, BK=32)
constexpr int NSTAGE = 3;
constexpr int DYN_SMEM = NSTAGE * STAGE;
}

__device__ __half g_xh[(size_t)Mm * Cc];     // 24000x1024
__device__ __half g_wbh[(size_t)Oo * Cc];    // 1024x1024
__device__ __half g_ah[(size_t)ER * Cc];     // 128x1024 (Acat)
__device__ __half g_bch[(size_t)Oo * ER];    // 1024x128 (Bcat)
__device__ __half g_Hh[(size_t)Mm * ER];     // 24000x128

// ---------------------------------------------------------------------------
__device__ __forceinline__ uint32_t smem_u32(const void* p) {
    uint32_t a;
    asm("{ .reg .u64 t; cvta.to.shared.u64 t, %1; cvt.u32.u64 %0, t; }" : "=r"(a) : "l"(p));
    return a;
}

#define CP16(s, g) \
    asm volatile("cp.async.cg.shared.global [%0], [%1], 16;" :: "r"(s), "l"(g))
#define CP_COMMIT() asm volatile("cp.async.commit_group;" ::: "memory")
#define CP_WAIT1() asm volatile("cp.async.wait_group 1;" ::: "memory")
#define CP_WAIT0() asm volatile("cp.async.wait_group 0;" ::: "memory")

#define LDSM_X4(r0, r1, r2, r3, a) \
    asm volatile("ldmatrix.sync.aligned.m8n8.x4.shared.b16 {%0,%1,%2,%3}, [%4];" \
                 : "=r"(r0), "=r"(r1), "=r"(r2), "=r"(r3) : "r"(a))

#define MMA_F16(d, a, b) \
    asm volatile("mma.sync.aligned.m16n8k16.row.col.f32.f16.f16.f32 " \
                 "{%0,%1,%2,%3},{%4,%5,%6,%7},{%8,%9},{%0,%1,%2,%3};" \
                 : "+f"((d)[0]), "+f"((d)[1]), "+f"((d)[2]), "+f"((d)[3]) \
                 : "r"((a)[0]), "r"((a)[1]), "r"((a)[2]), "r"((a)[3]), \
                   "r"((b)[0]), "r"((b)[1]))

// swizzled byte offset within an 8KB tile: 64B rows, 4x16B cols, xor swizzle
__device__ __forceinline__ uint32_t swz(int r, int c) {
    return (uint32_t)(r * 64 + ((c ^ ((r >> 1) & 3)) << 4));
}

// one BK=32 chunk: 2 k-steps x (4 m x 4 n) MMAs
__device__ __forceinline__ void compute_chunk(float (&acc)[4][4][4],
                                              uint32_t base,
                                              const uint32_t* offA,
                                              const uint32_t* offB) {
    const uint32_t aB = base, bB = base + 8192u;
#pragma unroll
    for (int ks = 0; ks < 2; ks++) {
        uint32_t aF[4][4], bF[4][2];
#pragma unroll
        for (int mi = 0; mi < 4; mi++)
            LDSM_X4(aF[mi][0], aF[mi][1], aF[mi][2], aF[mi][3], aB + offA[mi * 2 + ks]);
#pragma unroll
        for (int j = 0; j < 2; j++) {
            uint32_t t0, t1, t2, t3;
            LDSM_X4(t0, t1, t2, t3, bB + offB[j * 2 + ks]);
            bF[2 * j][0] = t0; bF[2 * j][1] = t1;
            bF[2 * j + 1][0] = t2; bF[2 * j + 1][1] = t3;
        }
#pragma unroll
        for (int mi = 0; mi < 4; mi++)
#pragma unroll
            for (int ni = 0; ni < 4; ni++)
                MMA_F16(acc[mi][ni], aF[mi], bF[ni]);
    }
}

__device__ __forceinline__ void make_offsets(int lane, int wm, int wn,
                                             uint32_t* offA, uint32_t* offB) {
    int g = lane >> 3, wr = lane & 7;
#pragma unroll
    for (int mi = 0; mi < 4; mi++)
#pragma unroll
        for (int ks = 0; ks < 2; ks++) {
            int r = wm * 64 + mi * 16 + (g & 1) * 8 + wr;
            offA[mi * 2 + ks] = swz(r, ks * 2 + (g >> 1));
        }
#pragma unroll
    for (int j = 0; j < 2; j++)
#pragma unroll
        for (int ks = 0; ks < 2; ks++) {
            int n = wn * 32 + j * 16 + (g >> 1) * 8 + wr;
            offB[j * 2 + ks] = swz(n, ks * 2 + (g & 1));
        }
}

// ---------------------------------------------------------------------------
// prep kernels — destination global resolved IN DEVICE CODE (never pass a
// __device__ symbol as a host-side kernel argument).
// ---------------------------------------------------------------------------
__global__ void k_cvt(const float* __restrict__ src, int which, int n4) {
    int i = blockIdx.x * blockDim.x + threadIdx.x;
    if (i >= n4) return;
    __half* dst = (which == 0) ? g_xh : (which == 1) ? g_wbh : g_ah;
    float4 v = *(const float4*)(src + (size_t)i * 4);
    __half2 h0 = __float22half2_rn(make_float2(v.x, v.y));
    __half2 h1 = __float22half2_rn(make_float2(v.z, v.w));
    uint32_t u0 = *(uint32_t*)&h0, u1 = *(uint32_t*)&h1;
    *(uint2*)(dst + (size_t)i * 4) = make_uint2(u0, u1);
}

__global__ void k_prep_bcat(const float* __restrict__ Bs) {
    int idx = blockIdx.x * blockDim.x + threadIdx.x;   // o*128 + n
    if (idx >= Oo * ER) return;
    int o = idx >> 7;
    int n = idx & 127;
    g_bch[idx] = __float2half(Bs[(((size_t)(n >> 4)) * Oo + o) * Rr + (n & 15)]);
}

// ---------------------------------------------------------------------------
// Kernel 1: Hh = gate-scaled (xh @ ah^T), 32 chunks of BK=32
// ---------------------------------------------------------------------------
__global__ __launch_bounds__(256, 2)
void k_lora_h(const float* __restrict__ w) {
    extern __shared__ char dsm[];
    const uint32_t sb = smem_u32(dsm);
    const int tid = threadIdx.x;
    const int lane = tid & 31, wid = tid >> 5;
    const int wm = wid >> 2, wn = wid & 3;
    const int bm = blockIdx.x * 128;

    // loader role: rows r0 and r0+64; cc4 = 16B column slot
    const int r0 = tid >> 2, cc4 = tid & 3;
    const __half* xa0 = g_xh + (size_t)min(bm + r0, Mm - 1) * Cc + cc4 * 8;
    const __half* xa1 = g_xh + (size_t)min(bm + r0 + 64, Mm - 1) * Cc + cc4 * 8;
    const __half* ab0 = g_ah + (size_t)r0 * Cc + cc4 * 8;
    const __half* ab1 = g_ah + (size_t)(r0 + 64) * Cc + cc4 * 8;
    const uint32_t o0 = swz(r0, cc4), o1 = swz(r0 + 64, cc4);

    uint32_t offA[8], offB[4];
    make_offsets(lane, wm, wn, offA, offB);

    float acc[4][4][4];
#pragma unroll
    for (int a = 0; a < 4; a++)
#pragma unroll
        for (int b = 0; b < 4; b++)
#pragma unroll
            for (int c = 0; c < 4; c++) acc[a][b][c] = 0.0f;

    const int NCH = 32;
#pragma unroll
    for (int p = 0; p < 2; p++) {
        uint32_t st = sb + (uint32_t)p * STAGE;
        CP16(st + o0, xa0 + p * 32); CP16(st + o1, xa1 + p * 32);
        CP16(st + 8192u + o0, ab0 + p * 32); CP16(st + 8192u + o1, ab1 + p * 32);
        CP_COMMIT();
    }

#pragma unroll 1
    for (int ch = 0; ch < NCH; ch++) {
        if (ch + 1 < NCH) CP_WAIT1(); else CP_WAIT0();
        __syncthreads();
        if (ch + 2 < NCH) {
            uint32_t st = sb + (uint32_t)((ch + 2) % NSTAGE) * STAGE;
            CP16(st + o0, xa0 + (ch + 2) * 32); CP16(st + o1, xa1 + (ch + 2) * 32);
            CP16(st + 8192u + o0, ab0 + (ch + 2) * 32); CP16(st + 8192u + o1, ab1 + (ch + 2) * 32);
            CP_COMMIT();
        }
        compute_chunk(acc, sb + (uint32_t)(ch % NSTAGE) * STAGE, offA, offB);
    }

    // epilogue: scale and store fp16 H
#pragma unroll
    for (int mi = 0; mi < 4; mi++) {
#pragma unroll
        for (int ni = 0; ni < 4; ni++) {
            int n = wn * 32 + ni * 8 + 2 * (lane & 3);
            int e = n >> 4;
            int m0 = bm + wm * 64 + mi * 16 + (lane >> 2);
            if (m0 < Mm) {
                float sw = SCALE * __ldg(&w[(m0 / Tt) * Ee + e]);
                __half2 h = __float22half2_rn(make_float2(acc[mi][ni][0] * sw, acc[mi][ni][1] * sw));
                *(__half2*)(&g_Hh[(size_t)m0 * ER + n]) = h;
            }
            int m1 = m0 + 8;
            if (m1 < Mm) {
                float sw = SCALE * __ldg(&w[(m1 / Tt) * Ee + e]);
                __half2 h = __float22half2_rn(make_float2(acc[mi][ni][2] * sw, acc[mi][ni][3] * sw));
                *(__half2*)(&g_Hh[(size_t)m1 * ER + n]) = h;
            }
        }
    }
}

// ---------------------------------------------------------------------------
// Kernel 2: out = xh @ wbh^T + Hh @ bch^T + bb; 36 chunks (32 base + 4 lora)
// ---------------------------------------------------------------------------
__global__ __launch_bounds__(256, 2)
void k_main(const float* __restrict__ bb, float* __restrict__ out) {
    extern __shared__ char dsm[];
    const uint32_t sb = smem_u32(dsm);
    const int tid = threadIdx.x;
    const int lane = tid & 31, wid = tid >> 5;
    const int wm = wid >> 2, wn = wid & 3;
    const int bn = blockIdx.x * 128;
    const int bm = blockIdx.y * 128;

    const int r0 = tid >> 2, cc4 = tid & 3;
    const size_t mA0 = (size_t)min(bm + r0, Mm - 1);
    const size_t mA1 = (size_t)min(bm + r0 + 64, Mm - 1);
    const __half* xa0 = g_xh + mA0 * Cc + cc4 * 8;
    const __half* xa1 = g_xh + mA1 * Cc + cc4 * 8;
    const __half* wb0 = g_wbh + (size_t)(bn + r0) * Cc + cc4 * 8;
    const __half* wb1 = g_wbh + (size_t)(bn + r0 + 64) * Cc + cc4 * 8;
    const __half* ha0 = g_Hh + mA0 * ER + cc4 * 8;
    const __half* ha1 = g_Hh + mA1 * ER + cc4 * 8;
    const __half* bc0 = g_bch + (size_t)(bn + r0) * ER + cc4 * 8;
    const __half* bc1 = g_bch + (size_t)(bn + r0 + 64) * ER + cc4 * 8;
    const uint32_t o0 = swz(r0, cc4), o1 = swz(r0 + 64, cc4);

    uint32_t offA[8], offB[4];
    make_offsets(lane, wm, wn, offA, offB);

    float acc[4][4][4];
#pragma unroll
    for (int a = 0; a < 4; a++)
#pragma unroll
        for (int b = 0; b < 4; b++)
#pragma unroll
            for (int c = 0; c < 4; c++) acc[a][b][c] = 0.0f;

    const int NCH = 36;

    auto issue = [&](int ch) {
        uint32_t st = sb + (uint32_t)(ch % NSTAGE) * STAGE;
        const __half *a0, *a1, *b0, *b1;
        if (ch < 32) {
            a0 = xa0 + ch * 32; a1 = xa1 + ch * 32;
            b0 = wb0 + ch * 32; b1 = wb1 + ch * 32;
        } else {
            int c2 = ch - 32;
            a0 = ha0 + c2 * 32; a1 = ha1 + c2 * 32;
            b0 = bc0 + c2 * 32; b1 = bc1 + c2 * 32;
        }
        CP16(st + o0, a0); CP16(st + o1, a1);
        CP16(st + 8192u + o0, b0); CP16(st + 8192u + o1, b1);
        CP_COMMIT();
    };

    issue(0);
    issue(1);

#pragma unroll 1
    for (int ch = 0; ch < NCH; ch++) {
        if (ch + 1 < NCH) CP_WAIT1(); else CP_WAIT0();
        __syncthreads();
        if (ch + 2 < NCH) issue(ch + 2);
        compute_chunk(acc, sb + (uint32_t)(ch % NSTAGE) * STAGE, offA, offB);
    }

    // epilogue: add bias, store fp32
#pragma unroll
    for (int mi = 0; mi < 4; mi++) {
#pragma unroll
        for (int ni = 0; ni < 4; ni++) {
            int col = bn + wn * 32 + ni * 8 + 2 * (lane & 3);
            float2 bias = *(const float2*)(bb + col);
            int m0 = bm + wm * 64 + mi * 16 + (lane >> 2);
            if (m0 < Mm) {
                float2 o = make_float2(acc[mi][ni][0] + bias.x, acc[mi][ni][1] + bias.y);
                *(float2*)(out + (size_t)m0 * Oo + col) = o;
            }
            int m1 = m0 + 8;
            if (m1 < Mm) {
                float2 o = make_float2(acc[mi][ni][2] + bias.x, acc[mi][ni][3] + bias.y);
                *(float2*)(out + (size_t)m1 * Oo + col) = o;
            }
        }
    }
}

// ---------------------------------------------------------------------------
extern "C" void kernel_launch(void* const* d_in, const int* in_sizes, int n_in,
                              void* d_out, int out_size) {
    const float* x  = (const float*)d_in[0];   // (16,1500,1024)
    const float* w  = (const float*)d_in[1];   // (16,8)
    const float* Wb = (const float*)d_in[2];   // (1024,1024)
    const float* bb = (const float*)d_in[3];   // (1024,)
    const float* As = (const float*)d_in[4];   // (8,16,1024) = Acat (128,1024)
    const float* Bs = (const float*)d_in[5];   // (8,1024,16)
    float* out = (float*)d_out;

    cudaFuncSetAttribute(k_lora_h, cudaFuncAttributeMaxDynamicSharedMemorySize, DYN_SMEM);
    cudaFuncSetAttribute(k_main, cudaFuncAttributeMaxDynamicSharedMemorySize, DYN_SMEM);

    // one-time conversions; destination picked in device code by `which`
    k_cvt<<<(Mm * Cc / 4 + 255) / 256, 256>>>(x, 0, Mm * Cc / 4);
    k_cvt<<<(Oo * Cc / 4 + 255) / 256, 256>>>(Wb, 1, Oo * Cc / 4);
    k_cvt<<<(ER * Cc / 4 + 255) / 256, 256>>>(As, 2, ER * Cc / 4);
    k_prep_bcat<<<(Oo * ER + 255) / 256, 256>>>(Bs);

    const int grid_m = (Mm + 127) / 128;  // 188
    k_lora_h<<<grid_m, 256, DYN_SMEM>>>(w);

    dim3 g2(Oo / 128, grid_m);            // (8, 188)
    k_main<<<g2, 256, DYN_SMEM>>>(bb, out);
}